// round 2
// baseline (speedup 1.0000x reference)
#include <cuda_runtime.h>
#include <math.h>

#define NN 20000
#define EE 320000
#define HH 64
#define MM 8
#define FEAT (HH*MM)          // 512 floats per node
#define NMINV (1.0f/(float)(NN*MM))
#define BN_EPS 1e-5f

// ---------------- scratch (device globals: allocation-free rule) ----------------
__device__ __align__(128) float g_h[NN*FEAT];     // current layer activations
__device__ __align__(128) float g_z[NN*FEAT];     // h + aggregated neighbors
__device__ __align__(128) float g_u[NN*FEAT];     // post-MLP (pre-BN-normalize)
__device__ __align__(128) int   g_rowptr[NN+1];
__device__ __align__(128) int   g_cnt[NN];
__device__ __align__(128) int   g_col[EE];
__device__ __align__(128) float g_stats[2*HH];    // per-channel sum / sumsq
__device__ __align__(128) float g_scale[HH];
__device__ __align__(128) float g_shift[HH];
__device__ __align__(128) float g_pool[FEAT];

// ---------------- CSR build ----------------
__global__ void k_zero_init() {
    int i = blockIdx.x*blockDim.x + threadIdx.x;
    if (i < NN)   g_cnt[i] = 0;
    if (i < FEAT) g_pool[i] = 0.f;
}

__global__ void k_hist(const int* __restrict__ ei) {
    int e = blockIdx.x*blockDim.x + threadIdx.x;
    if (e < EE) atomicAdd(&g_cnt[ei[EE + e]], 1);   // dst row
}

// single-block exclusive scan of g_cnt -> g_rowptr, re-zero g_cnt for fill pass
__global__ void k_scan() {
    __shared__ int sh[1024];
    const int PER = (NN + 1023) / 1024;   // 20
    int tid = threadIdx.x;
    int base = tid * PER;
    int s = 0;
    for (int i = 0; i < PER; ++i) {
        int idx = base + i;
        if (idx < NN) s += g_cnt[idx];
    }
    sh[tid] = s;
    __syncthreads();
    for (int off = 1; off < 1024; off <<= 1) {
        int t = 0;
        if (tid >= off) t = sh[tid - off];
        __syncthreads();
        sh[tid] += t;
        __syncthreads();
    }
    int run = sh[tid] - s;                 // exclusive prefix of this chunk
    for (int i = 0; i < PER; ++i) {
        int idx = base + i;
        if (idx < NN) {
            int c = g_cnt[idx];
            g_rowptr[idx] = run;
            run += c;
            g_cnt[idx] = 0;
        }
    }
    if (tid == 1023) g_rowptr[NN] = sh[1023];
}

__global__ void k_fill(const int* __restrict__ ei) {
    int e = blockIdx.x*blockDim.x + threadIdx.x;
    if (e < EE) {
        int d = ei[EE + e];
        int pos = g_rowptr[d] + atomicAdd(&g_cnt[d], 1);
        g_col[pos] = ei[e];                // src row
    }
}

// ---------------- aggregation ----------------
// layer 0: x is [N,1,M] -> 8 floats per node
__global__ void k_agg0(const float* __restrict__ x) {
    int n = blockIdx.x*blockDim.x + threadIdx.x;
    if (n >= NN) return;
    float4 a0 = *(const float4*)&x[n*MM];
    float4 a1 = *(const float4*)&x[n*MM + 4];
    int beg = g_rowptr[n], end = g_rowptr[n+1];
    for (int j = beg; j < end; ++j) {
        int s = g_col[j];
        float4 v0 = *(const float4*)&x[s*MM];
        float4 v1 = *(const float4*)&x[s*MM + 4];
        a0.x += v0.x; a0.y += v0.y; a0.z += v0.z; a0.w += v0.w;
        a1.x += v1.x; a1.y += v1.y; a1.z += v1.z; a1.w += v1.w;
    }
    *(float4*)&g_z[n*MM]     = a0;
    *(float4*)&g_z[n*MM + 4] = a1;
}

// layers >=1: block per node, 128 threads x float4 over 512 feats
__global__ void k_agg() {
    int n   = blockIdx.x;
    int off = threadIdx.x * 4;
    float4 a = *(const float4*)&g_h[n*FEAT + off];
    float4 b = make_float4(0.f, 0.f, 0.f, 0.f);
    int beg = g_rowptr[n], end = g_rowptr[n+1];
    int j = beg;
    for (; j + 1 < end; j += 2) {
        int s0 = g_col[j], s1 = g_col[j+1];
        float4 v0 = *(const float4*)&g_h[s0*FEAT + off];
        float4 v1 = *(const float4*)&g_h[s1*FEAT + off];
        a.x += v0.x; a.y += v0.y; a.z += v0.z; a.w += v0.w;
        b.x += v1.x; b.y += v1.y; b.z += v1.z; b.w += v1.w;
    }
    if (j < end) {
        int s0 = g_col[j];
        float4 v0 = *(const float4*)&g_h[s0*FEAT + off];
        a.x += v0.x; a.y += v0.y; a.z += v0.z; a.w += v0.w;
    }
    a.x += b.x; a.y += b.y; a.z += b.z; a.w += b.w;
    *(float4*)&g_z[n*FEAT + off] = a;
}

// ---------------- MLP (2 GEMMs + relu + BN-stat accumulation) ----------------
__global__ void k_zero_stats() {
    if (threadIdx.x < 2*HH) g_stats[threadIdx.x] = 0.f;
}

template<int CIN>
__global__ void __launch_bounds__(256) k_mlp(
    const float* __restrict__ w1, const float* __restrict__ b1,
    const float* __restrict__ w2, const float* __restrict__ b2,
    int zstride)
{
    __shared__ float w1s[CIN*HH];       // transposed: w1s[c*64+o] = W1[o][c]
    __shared__ float w2s[HH*HH];        // transposed
    __shared__ float b1s[HH], b2s[HH];
    __shared__ float zs[2][CIN*MM];
    __shared__ float ts[2][HH*MM];
    __shared__ float shst[2*HH];

    int tid = threadIdx.x;
    for (int idx = tid; idx < CIN*HH; idx += 256) {
        int o = idx & 63, c = idx >> 6;
        w1s[idx] = w1[o*CIN + c];
    }
    for (int idx = tid; idx < HH*HH; idx += 256) {
        int o = idx & 63, c = idx >> 6;
        w2s[idx] = w2[o*HH + c];
    }
    if (tid < HH)   { b1s[tid] = b1[tid]; b2s[tid] = b2[tid]; }
    if (tid < 2*HH) shst[tid] = 0.f;
    __syncthreads();

    int g  = tid >> 7;            // node-group 0/1 (128 threads each)
    int t  = tid & 127;
    int o  = t >> 1;              // output channel
    int mh = (t & 1) * 4;         // m-half
    float lsum = 0.f, lsq = 0.f;

    for (int it = 0; it < 8; ++it) {
        int n = blockIdx.x*16 + g*8 + it;
        // load z tile for this node
        #pragma unroll
        for (int idx = t; idx < CIN*2; idx += 128) {
            *(float4*)&zs[g][idx*4] = *(const float4*)&g_z[n*zstride + idx*4];
        }
        __syncthreads();
        // GEMM1 + relu
        float bb = b1s[o];
        float4 acc = make_float4(bb, bb, bb, bb);
        #pragma unroll
        for (int c = 0; c < CIN; ++c) {
            float w = w1s[c*HH + o];
            float4 zv = *(const float4*)&zs[g][c*MM + mh];
            acc.x = fmaf(w, zv.x, acc.x);
            acc.y = fmaf(w, zv.y, acc.y);
            acc.z = fmaf(w, zv.z, acc.z);
            acc.w = fmaf(w, zv.w, acc.w);
        }
        acc.x = fmaxf(acc.x, 0.f); acc.y = fmaxf(acc.y, 0.f);
        acc.z = fmaxf(acc.z, 0.f); acc.w = fmaxf(acc.w, 0.f);
        *(float4*)&ts[g][o*MM + mh] = acc;
        __syncthreads();
        // GEMM2 + relu
        float b2v = b2s[o];
        float4 a2 = make_float4(b2v, b2v, b2v, b2v);
        #pragma unroll
        for (int c = 0; c < HH; ++c) {
            float w = w2s[c*HH + o];
            float4 tv = *(const float4*)&ts[g][c*MM + mh];
            a2.x = fmaf(w, tv.x, a2.x);
            a2.y = fmaf(w, tv.y, a2.y);
            a2.z = fmaf(w, tv.z, a2.z);
            a2.w = fmaf(w, tv.w, a2.w);
        }
        a2.x = fmaxf(a2.x, 0.f); a2.y = fmaxf(a2.y, 0.f);
        a2.z = fmaxf(a2.z, 0.f); a2.w = fmaxf(a2.w, 0.f);
        *(float4*)&g_u[n*FEAT + o*MM + mh] = a2;
        lsum += a2.x + a2.y + a2.z + a2.w;
        lsq  += a2.x*a2.x + a2.y*a2.y + a2.z*a2.z + a2.w*a2.w;
    }
    atomicAdd(&shst[o],      lsum);
    atomicAdd(&shst[HH + o], lsq);
    __syncthreads();
    if (tid < 2*HH) atomicAdd(&g_stats[tid], shst[tid]);
}

// ---------------- BN ----------------
__global__ void k_bnparams(const float* __restrict__ gamma,
                           const float* __restrict__ beta) {
    int c = threadIdx.x;
    if (c < HH) {
        float s  = g_stats[c];
        float ss = g_stats[HH + c];
        float mean = s * NMINV;
        float var  = ss * NMINV - mean*mean;
        float r  = rsqrtf(var + BN_EPS);
        float sc = gamma[c] * r;
        g_scale[c] = sc;
        g_shift[c] = beta[c] - mean*sc;
    }
}

__global__ void k_bnapply() {
    int idx = blockIdx.x*blockDim.x + threadIdx.x;   // 2,560,000 threads
    int e = idx * 4;
    int c = (e >> 3) & 63;
    float sc = g_scale[c], sh = g_shift[c];
    float4 v = *(const float4*)&g_u[e];
    v.x = v.x*sc + sh; v.y = v.y*sc + sh;
    v.z = v.z*sc + sh; v.w = v.w*sc + sh;
    *(float4*)&g_h[e] = v;
}

// ---------------- pooling + head ----------------
__global__ void k_pool() {
    int cm = threadIdx.x;                // 512 threads: one (c,m)
    int nb = blockIdx.x * 128;
    int ne = min(nb + 128, NN);
    float acc = 0.f;
    for (int n = nb; n < ne; ++n) acc += g_h[n*FEAT + cm];
    atomicAdd(&g_pool[cm], acc);
}

__global__ void k_out(const float* __restrict__ w_out,
                      const float* __restrict__ b_out,
                      float* __restrict__ out) {
    int m = threadIdx.x;
    if (m < MM) {
        float acc = 0.f;
        for (int h = 0; h < HH; ++h) acc += w_out[h] * g_pool[h*MM + m];
        float v = acc / (float)NN + b_out[0];
        out[m] = 1.f / (1.f + expf(-v));
    }
}

// ---------------- launch ----------------
extern "C" void kernel_launch(void* const* d_in, const int* in_sizes, int n_in,
                              void* d_out, int out_size) {
    const float* x     = (const float*)d_in[0];
    const int*   ei    = (const int*)d_in[1];     // int32 (JAX x64 disabled)
    // d_in[2] = batch (all zeros, unused)
    const float* w1_0  = (const float*)d_in[3];
    const float* w1    = (const float*)d_in[4];
    const float* b1    = (const float*)d_in[5];
    const float* w2    = (const float*)d_in[6];
    const float* b2    = (const float*)d_in[7];
    const float* gamma = (const float*)d_in[8];
    const float* beta  = (const float*)d_in[9];
    const float* w_out = (const float*)d_in[10];
    const float* b_out = (const float*)d_in[11];
    float*       out   = (float*)d_out;

    // CSR build (per launch; no caching allowed)
    k_zero_init<<<(NN + 255)/256, 256>>>();
    k_hist<<<(EE + 255)/256, 256>>>(ei);
    k_scan<<<1, 1024>>>();
    k_fill<<<(EE + 255)/256, 256>>>(ei);

    // layer 0 (cin = 1)
    k_agg0<<<(NN + 255)/256, 256>>>(x);
    k_zero_stats<<<1, 128>>>();
    k_mlp<1><<<NN/16, 256>>>(w1_0, b1, w2, b2, MM);
    k_bnparams<<<1, 64>>>(gamma, beta);
    k_bnapply<<<NN*FEAT/(4*256), 256>>>();

    // layers 1..4 (cin = 64)
    for (int i = 1; i < 5; ++i) {
        k_agg<<<NN, 128>>>();
        k_zero_stats<<<1, 128>>>();
        k_mlp<HH><<<NN/16, 256>>>(w1 + (i-1)*HH*HH, b1 + i*HH,
                                  w2 + i*HH*HH,     b2 + i*HH, FEAT);
        k_bnparams<<<1, 64>>>(gamma + i*HH, beta + i*HH);
        k_bnapply<<<NN*FEAT/(4*256), 256>>>();
    }

    // global mean pool + sigmoid head
    k_pool<<<(NN + 127)/128, 512>>>();
    k_out<<<1, 32>>>(w_out, b_out, out);
}

// round 3
// speedup vs baseline: 1.2889x; 1.2889x over previous
#include <cuda_runtime.h>
#include <math.h>

#define NN 20000
#define EE 320000
#define HH 64
#define MM 8
#define FEAT (HH*MM)          // 512 floats per node
#define NMINV (1.0f/(float)(NN*MM))
#define BN_EPS 1e-5f

// ---------------- scratch (device globals: allocation-free rule) ----------------
__device__ __align__(128) float g_z[NN*FEAT];     // aggregated input to MLP
__device__ __align__(128) float g_u[NN*FEAT];     // raw MLP output (pre-BN)
__device__ __align__(128) int   g_rowptr[NN+1];
__device__ __align__(128) int   g_cnt[NN];
__device__ __align__(128) int   g_col[EE];
__device__ __align__(128) float g_stats[2*HH];    // per-channel sum / sumsq
__device__ __align__(128) float g_scale[HH];
__device__ __align__(128) float g_shift[HH];
__device__ __align__(128) float g_pool[FEAT];

// ---------------- CSR build ----------------
__global__ void k_zero_init() {
    int i = blockIdx.x*blockDim.x + threadIdx.x;
    if (i < NN)   g_cnt[i] = 0;
    if (i < FEAT) g_pool[i] = 0.f;
    if (i < 2*HH) g_stats[i] = 0.f;
}

__global__ void k_hist(const int* __restrict__ ei) {
    int e = blockIdx.x*blockDim.x + threadIdx.x;
    if (e < EE) atomicAdd(&g_cnt[ei[EE + e]], 1);   // dst row
}

__global__ void k_scan() {
    __shared__ int sh[1024];
    const int PER = (NN + 1023) / 1024;   // 20
    int tid = threadIdx.x;
    int base = tid * PER;
    int s = 0;
    for (int i = 0; i < PER; ++i) {
        int idx = base + i;
        if (idx < NN) s += g_cnt[idx];
    }
    sh[tid] = s;
    __syncthreads();
    for (int off = 1; off < 1024; off <<= 1) {
        int t = 0;
        if (tid >= off) t = sh[tid - off];
        __syncthreads();
        sh[tid] += t;
        __syncthreads();
    }
    int run = sh[tid] - s;
    for (int i = 0; i < PER; ++i) {
        int idx = base + i;
        if (idx < NN) {
            int c = g_cnt[idx];
            g_rowptr[idx] = run;
            run += c;
            g_cnt[idx] = 0;
        }
    }
    if (tid == 1023) g_rowptr[NN] = sh[1023];
}

__global__ void k_fill(const int* __restrict__ ei) {
    int e = blockIdx.x*blockDim.x + threadIdx.x;
    if (e < EE) {
        int d = ei[EE + e];
        int pos = g_rowptr[d] + atomicAdd(&g_cnt[d], 1);
        g_col[pos] = ei[e];
    }
}

// ---------------- aggregation ----------------
// layer 0: x is [N,1,M]; z = x_self + sum x_nbr (no BN)
__global__ void k_agg0(const float* __restrict__ x) {
    int n = blockIdx.x*blockDim.x + threadIdx.x;
    if (n >= NN) return;
    float4 a0 = *(const float4*)&x[n*MM];
    float4 a1 = *(const float4*)&x[n*MM + 4];
    int beg = g_rowptr[n], end = g_rowptr[n+1];
    for (int j = beg; j < end; ++j) {
        int s = g_col[j];
        float4 v0 = *(const float4*)&x[s*MM];
        float4 v1 = *(const float4*)&x[s*MM + 4];
        a0.x += v0.x; a0.y += v0.y; a0.z += v0.z; a0.w += v0.w;
        a1.x += v1.x; a1.y += v1.y; a1.z += v1.z; a1.w += v1.w;
    }
    *(float4*)&g_z[n*MM]     = a0;
    *(float4*)&g_z[n*MM + 4] = a1;
}

// layers >=1: fused BN + aggregation:
// z = scale_c * (u_self + sum u_nbr) + (deg+1) * shift_c
__global__ void k_aggbn() {
    int n   = blockIdx.x;
    int off = threadIdx.x * 4;          // 128 threads x float4
    int c   = off >> 3;                 // channel ([c][m] layout)
    float sc = g_scale[c];
    float sh = g_shift[c];
    float4 a = *(const float4*)&g_u[n*FEAT + off];
    float4 b = make_float4(0.f, 0.f, 0.f, 0.f);
    int beg = g_rowptr[n], end = g_rowptr[n+1];
    int j = beg;
    for (; j + 1 < end; j += 2) {
        int s0 = g_col[j], s1 = g_col[j+1];
        float4 v0 = *(const float4*)&g_u[s0*FEAT + off];
        float4 v1 = *(const float4*)&g_u[s1*FEAT + off];
        a.x += v0.x; a.y += v0.y; a.z += v0.z; a.w += v0.w;
        b.x += v1.x; b.y += v1.y; b.z += v1.z; b.w += v1.w;
    }
    if (j < end) {
        int s0 = g_col[j];
        float4 v0 = *(const float4*)&g_u[s0*FEAT + off];
        a.x += v0.x; a.y += v0.y; a.z += v0.z; a.w += v0.w;
    }
    float cnt = (float)(end - beg + 1);
    float add = cnt * sh;
    a.x = fmaf(sc, a.x + b.x, add);
    a.y = fmaf(sc, a.y + b.y, add);
    a.z = fmaf(sc, a.z + b.z, add);
    a.w = fmaf(sc, a.w + b.w, add);
    *(float4*)&g_z[n*FEAT + off] = a;
}

// ---------------- MLP: register-tiled double GEMM + relu + BN stats ----------------
// 256 threads, 16 nodes/wave, 4 waves => 64 nodes/block.
// Thread t: node_local = t>>4, sub = t&15, handles o = 4*sub..4*sub+3, all 8 m.
template<int CIN>
__global__ void __launch_bounds__(256, 2) k_mlp(
    const float* __restrict__ w1, const float* __restrict__ b1,
    const float* __restrict__ w2, const float* __restrict__ b2)
{
    const int ZROW = CIN*MM + 4;        // padded node-row in smem (bank-skew)
    const int TROW = HH*MM + 4;         // 516

    extern __shared__ float dsm[];
    float* w1s = dsm;                   // [c][o] : CIN*64
    float* w2s = w1s + CIN*HH;          // [c][o] : 64*64
    float* zs  = w2s + HH*HH;           // 16 * ZROW   ([node][c][m])
    float* ts  = zs + 16*ZROW;          // 16 * TROW   ([node][m][o])
    __shared__ float b1s[HH], b2s[HH], shst[2*HH];

    int tid = threadIdx.x;
    for (int idx = tid; idx < CIN*HH; idx += 256) {
        int o = idx & 63, c = idx >> 6;
        w1s[idx] = w1[o*CIN + c];
    }
    for (int idx = tid; idx < HH*HH; idx += 256) {
        int o = idx & 63, c = idx >> 6;
        w2s[idx] = w2[o*HH + c];
    }
    if (tid < HH)   { b1s[tid] = b1[tid]; b2s[tid] = b2[tid]; }
    if (tid < 2*HH) shst[tid] = 0.f;
    __syncthreads();

    int nl  = tid >> 4;
    int sub = tid & 15;
    int o0  = sub * 4;
    float ssum[4] = {0.f,0.f,0.f,0.f};
    float ssq [4] = {0.f,0.f,0.f,0.f};

    for (int w = 0; w < 4; ++w) {
        int base = blockIdx.x*64 + w*16;
        // ---- stage z tile ----
        const int TOT = 16*CIN*2;   // float4 count
        for (int idx = tid; idx < TOT; idx += 256) {
            int node_l = idx / (CIN*2);
            int r      = idx - node_l*(CIN*2);
            int n      = base + node_l;
            float4 v = make_float4(0.f,0.f,0.f,0.f);
            if (n < NN) v = *(const float4*)&g_z[n*(CIN*MM) + r*4];
            *(float4*)&zs[node_l*ZROW + r*4] = v;
        }
        __syncthreads();

        int n = base + nl;
        // ---- GEMM1: t[o][m] = relu(b1 + sum_c w1[o][c] z[c][m]) ----
        float acc1[4][8];
        #pragma unroll
        for (int jo = 0; jo < 4; ++jo) {
            float bb = b1s[o0+jo];
            #pragma unroll
            for (int m = 0; m < 8; ++m) acc1[jo][m] = bb;
        }
        #pragma unroll 4
        for (int c = 0; c < CIN; ++c) {
            float4 wv = *(const float4*)&w1s[c*HH + o0];
            float wj[4] = {wv.x, wv.y, wv.z, wv.w};
            float4 zl = *(const float4*)&zs[nl*ZROW + c*MM];
            float4 zh = *(const float4*)&zs[nl*ZROW + c*MM + 4];
            float zm[8] = {zl.x,zl.y,zl.z,zl.w, zh.x,zh.y,zh.z,zh.w};
            #pragma unroll
            for (int jo = 0; jo < 4; ++jo)
                #pragma unroll
                for (int m = 0; m < 8; ++m)
                    acc1[jo][m] = fmaf(wj[jo], zm[m], acc1[jo][m]);
        }
        // relu + write t in [m][o] layout (float4 over o)
        #pragma unroll
        for (int m = 0; m < 8; ++m) {
            float4 v = make_float4(fmaxf(acc1[0][m],0.f), fmaxf(acc1[1][m],0.f),
                                   fmaxf(acc1[2][m],0.f), fmaxf(acc1[3][m],0.f));
            *(float4*)&ts[nl*TROW + m*HH + o0] = v;
        }
        __syncthreads();

        // ---- GEMM2: u[o][m] = relu(b2 + sum_c w2[o][c] t[c][m]) ----
        float acc2[4][8];
        #pragma unroll
        for (int jo = 0; jo < 4; ++jo) {
            float bb = b2s[o0+jo];
            #pragma unroll
            for (int m = 0; m < 8; ++m) acc2[jo][m] = bb;
        }
        #pragma unroll 2
        for (int c0 = 0; c0 < HH; c0 += 4) {
            float tq[8][4];
            #pragma unroll
            for (int m = 0; m < 8; ++m) {
                float4 t4 = *(const float4*)&ts[nl*TROW + m*HH + c0];
                tq[m][0]=t4.x; tq[m][1]=t4.y; tq[m][2]=t4.z; tq[m][3]=t4.w;
            }
            float wq[4][4];
            #pragma unroll
            for (int jc = 0; jc < 4; ++jc) {
                float4 wv = *(const float4*)&w2s[(c0+jc)*HH + o0];
                wq[jc][0]=wv.x; wq[jc][1]=wv.y; wq[jc][2]=wv.z; wq[jc][3]=wv.w;
            }
            #pragma unroll
            for (int jc = 0; jc < 4; ++jc)
                #pragma unroll
                for (int jo = 0; jo < 4; ++jo)
                    #pragma unroll
                    for (int m = 0; m < 8; ++m)
                        acc2[jo][m] = fmaf(tq[m][jc], wq[jc][jo], acc2[jo][m]);
        }
        // relu + store u ([c][m] layout) + stats
        if (n < NN) {
            #pragma unroll
            for (int jo = 0; jo < 4; ++jo) {
                float v0 = fmaxf(acc2[jo][0],0.f), v1 = fmaxf(acc2[jo][1],0.f);
                float v2 = fmaxf(acc2[jo][2],0.f), v3 = fmaxf(acc2[jo][3],0.f);
                float v4 = fmaxf(acc2[jo][4],0.f), v5 = fmaxf(acc2[jo][5],0.f);
                float v6 = fmaxf(acc2[jo][6],0.f), v7 = fmaxf(acc2[jo][7],0.f);
                *(float4*)&g_u[n*FEAT + (o0+jo)*MM]     = make_float4(v0,v1,v2,v3);
                *(float4*)&g_u[n*FEAT + (o0+jo)*MM + 4] = make_float4(v4,v5,v6,v7);
                ssum[jo] += v0+v1+v2+v3+v4+v5+v6+v7;
                ssq[jo]  += v0*v0+v1*v1+v2*v2+v3*v3+v4*v4+v5*v5+v6*v6+v7*v7;
            }
        }
        __syncthreads();   // protect ts/zs for next wave
    }

    #pragma unroll
    for (int jo = 0; jo < 4; ++jo) {
        atomicAdd(&shst[o0+jo],      ssum[jo]);
        atomicAdd(&shst[HH+o0+jo],   ssq[jo]);
    }
    __syncthreads();
    if (tid < 2*HH) atomicAdd(&g_stats[tid], shst[tid]);
}

// ---------------- BN params (also resets stats for next layer) ----------------
__global__ void k_bnparams(const float* __restrict__ gamma,
                           const float* __restrict__ beta) {
    int c = threadIdx.x;
    if (c < HH) {
        float s  = g_stats[c];
        float ss = g_stats[HH + c];
        g_stats[c] = 0.f;
        g_stats[HH + c] = 0.f;
        float mean = s * NMINV;
        float var  = ss * NMINV - mean*mean;
        float r  = rsqrtf(var + BN_EPS);
        float sc = gamma[c] * r;
        g_scale[c] = sc;
        g_shift[c] = beta[c] - mean*sc;
    }
}

// ---------------- pooling + head ----------------
__global__ void k_pool() {
    int cm = threadIdx.x;                // 512 threads: one (c,m)
    int nb = blockIdx.x * 128;
    int ne = min(nb + 128, NN);
    float acc = 0.f;
    for (int n = nb; n < ne; ++n) acc += g_u[n*FEAT + cm];
    atomicAdd(&g_pool[cm], acc);
}

__global__ void k_out(const float* __restrict__ w_out,
                      const float* __restrict__ b_out,
                      float* __restrict__ out) {
    int m = threadIdx.x;
    if (m < MM) {
        float acc = 0.f;
        for (int h = 0; h < HH; ++h) {
            float ph = fmaf(g_scale[h], g_pool[h*MM + m] / (float)NN, g_shift[h]);
            acc += w_out[h] * ph;
        }
        float v = acc + b_out[0];
        out[m] = 1.f / (1.f + expf(-v));
    }
}

// ---------------- launch ----------------
extern "C" void kernel_launch(void* const* d_in, const int* in_sizes, int n_in,
                              void* d_out, int out_size) {
    const float* x     = (const float*)d_in[0];
    const int*   ei    = (const int*)d_in[1];     // int32 (JAX x64 disabled)
    const float* w1_0  = (const float*)d_in[3];
    const float* w1    = (const float*)d_in[4];
    const float* b1    = (const float*)d_in[5];
    const float* w2    = (const float*)d_in[6];
    const float* b2    = (const float*)d_in[7];
    const float* gamma = (const float*)d_in[8];
    const float* beta  = (const float*)d_in[9];
    const float* w_out = (const float*)d_in[10];
    const float* b_out = (const float*)d_in[11];
    float*       out   = (float*)d_out;

    // dynamic smem sizes
    const int SM1  = (1*HH  + HH*HH + 16*(1*MM+4)  + 16*(HH*MM+4)) * 4;   //  50 KB
    const int SM64 = (HH*HH + HH*HH + 16*(HH*MM+4) + 16*(HH*MM+4)) * 4;   //  ~97 KB
    // first (non-captured) correctness call sets these persistently
    cudaFuncSetAttribute(k_mlp<1>,  cudaFuncAttributeMaxDynamicSharedMemorySize, SM1);
    cudaFuncSetAttribute(k_mlp<HH>, cudaFuncAttributeMaxDynamicSharedMemorySize, SM64);

    // CSR build
    k_zero_init<<<(NN + 255)/256, 256>>>();
    k_hist<<<(EE + 255)/256, 256>>>(ei);
    k_scan<<<1, 1024>>>();
    k_fill<<<(EE + 255)/256, 256>>>(ei);

    const int MLPG = (NN + 63)/64;     // 313 blocks

    // layer 0 (cin = 1)
    k_agg0<<<(NN + 255)/256, 256>>>(x);
    k_mlp<1><<<MLPG, 256, SM1>>>(w1_0, b1, w2, b2);
    k_bnparams<<<1, 64>>>(gamma, beta);

    // layers 1..4 (cin = 64)
    for (int i = 1; i < 5; ++i) {
        k_aggbn<<<NN, 128>>>();
        k_mlp<HH><<<MLPG, 256, SM64>>>(w1 + (i-1)*HH*HH, b1 + i*HH,
                                       w2 + i*HH*HH,     b2 + i*HH);
        k_bnparams<<<1, 64>>>(gamma + i*HH, beta + i*HH);
    }

    // global mean pool + sigmoid head (affine of layer 4 folded in)
    k_pool<<<(NN + 127)/128, 512>>>();
    k_out<<<1, 32>>>(w_out, b_out, out);
}

// round 5
// speedup vs baseline: 1.5934x; 1.2362x over previous
#include <cuda_runtime.h>
#include <cuda_fp16.h>
#include <math.h>

#define NN 20000
#define EE 320000
#define HH 64
#define MM 8
#define FEAT (HH*MM)          // 512 elems per node
#define NMINV (1.0f/(float)(NN*MM))
#define BN_EPS 1e-5f

typedef unsigned long long u64;

// packed fp32x2 helpers (Blackwell): d = a*b + d (elementwise on 2 lanes)
#define FMA2(d,a,b)   asm("fma.rn.f32x2 %0,%1,%2,%0;" : "+l"(d) : "l"(a), "l"(b))
#define DUP2(d,s)     asm("mov.b64 %0,{%1,%1};"       : "=l"(d) : "f"(s))
#define UNP2(lo,hi,s) asm("mov.b64 {%0,%1},%2;" : "=f"(lo), "=f"(hi) : "l"(s))

// ---------------- scratch ----------------
__device__ __align__(128) float  g_z[NN*FEAT];    // fp32 input to MLP
__device__ __align__(128) __half g_uh[NN*FEAT];   // fp16 MLP output (pre-BN)
__device__ __align__(128) int    g_rowptr[NN+1];
__device__ __align__(128) int    g_cnt[NN];
__device__ __align__(128) int    g_col[EE];
__device__ __align__(128) float  g_stats[2*HH];
__device__ __align__(128) float  g_scale[HH];
__device__ __align__(128) float  g_shift[HH];
__device__ __align__(128) float  g_pool[FEAT];

// ---------------- CSR build ----------------
__global__ void k_zero_init() {
    int i = blockIdx.x*blockDim.x + threadIdx.x;
    if (i < NN)   g_cnt[i] = 0;
    if (i < FEAT) g_pool[i] = 0.f;
    if (i < 2*HH) g_stats[i] = 0.f;
}

__global__ void k_hist(const int* __restrict__ ei) {
    int e = blockIdx.x*blockDim.x + threadIdx.x;
    if (e < EE) atomicAdd(&g_cnt[ei[EE + e]], 1);
}

__global__ void k_scan() {
    __shared__ int sh[1024];
    const int PER = (NN + 1023) / 1024;
    int tid = threadIdx.x;
    int base = tid * PER;
    int s = 0;
    for (int i = 0; i < PER; ++i) {
        int idx = base + i;
        if (idx < NN) s += g_cnt[idx];
    }
    sh[tid] = s;
    __syncthreads();
    for (int off = 1; off < 1024; off <<= 1) {
        int t = 0;
        if (tid >= off) t = sh[tid - off];
        __syncthreads();
        sh[tid] += t;
        __syncthreads();
    }
    int run = sh[tid] - s;
    for (int i = 0; i < PER; ++i) {
        int idx = base + i;
        if (idx < NN) {
            int c = g_cnt[idx];
            g_rowptr[idx] = run;
            run += c;
            g_cnt[idx] = 0;
        }
    }
    if (tid == 1023) g_rowptr[NN] = sh[1023];
}

__global__ void k_fill(const int* __restrict__ ei) {
    int e = blockIdx.x*blockDim.x + threadIdx.x;
    if (e < EE) {
        int d = ei[EE + e];
        int pos = g_rowptr[d] + atomicAdd(&g_cnt[d], 1);
        g_col[pos] = ei[e];
    }
}

// ---------------- aggregation ----------------
__global__ void k_agg0(const float* __restrict__ x) {
    int n = blockIdx.x*blockDim.x + threadIdx.x;
    if (n >= NN) return;
    float4 a0 = *(const float4*)&x[n*MM];
    float4 a1 = *(const float4*)&x[n*MM + 4];
    int beg = g_rowptr[n], end = g_rowptr[n+1];
    for (int j = beg; j < end; ++j) {
        int s = g_col[j];
        float4 v0 = *(const float4*)&x[s*MM];
        float4 v1 = *(const float4*)&x[s*MM + 4];
        a0.x += v0.x; a0.y += v0.y; a0.z += v0.z; a0.w += v0.w;
        a1.x += v1.x; a1.y += v1.y; a1.z += v1.z; a1.w += v1.w;
    }
    *(float4*)&g_z[n*MM]     = a0;
    *(float4*)&g_z[n*MM + 4] = a1;
}

// fused BN + aggregation over fp16 u:
// z = scale_c * (u_self + sum u_nbr) + (deg+1) * shift_c
__global__ void k_aggbn() {
    int n  = blockIdx.x;
    int t  = threadIdx.x;          // 128 threads x 4 halves
    int h4 = t * 4;
    int c  = t >> 1;
    float sc = g_scale[c];
    float sh = g_shift[c];
    float4 a, b = make_float4(0.f,0.f,0.f,0.f);
    {
        uint2 r = *(const uint2*)&g_uh[n*FEAT + h4];
        float2 f0 = __half22float2(*(__half2*)&r.x);
        float2 f1 = __half22float2(*(__half2*)&r.y);
        a = make_float4(f0.x, f0.y, f1.x, f1.y);
    }
    int beg = g_rowptr[n], end = g_rowptr[n+1];
    int j = beg;
    for (; j + 1 < end; j += 2) {
        int s0 = g_col[j], s1 = g_col[j+1];
        uint2 r0 = *(const uint2*)&g_uh[s0*FEAT + h4];
        uint2 r1 = *(const uint2*)&g_uh[s1*FEAT + h4];
        float2 p0 = __half22float2(*(__half2*)&r0.x);
        float2 p1 = __half22float2(*(__half2*)&r0.y);
        float2 q0 = __half22float2(*(__half2*)&r1.x);
        float2 q1 = __half22float2(*(__half2*)&r1.y);
        a.x += p0.x; a.y += p0.y; a.z += p1.x; a.w += p1.y;
        b.x += q0.x; b.y += q0.y; b.z += q1.x; b.w += q1.y;
    }
    if (j < end) {
        int s0 = g_col[j];
        uint2 r0 = *(const uint2*)&g_uh[s0*FEAT + h4];
        float2 p0 = __half22float2(*(__half2*)&r0.x);
        float2 p1 = __half22float2(*(__half2*)&r0.y);
        a.x += p0.x; a.y += p0.y; a.z += p1.x; a.w += p1.y;
    }
    float cnt = (float)(end - beg + 1);
    float add = cnt * sh;
    a.x = fmaf(sc, a.x + b.x, add);
    a.y = fmaf(sc, a.y + b.y, add);
    a.z = fmaf(sc, a.z + b.z, add);
    a.w = fmaf(sc, a.w + b.w, add);
    *(float4*)&g_z[n*FEAT + h4] = a;
}

// ---------------- MLP: FFMA2 register-tiled double GEMM + relu + BN stats ----------------
// 256 threads, 16 nodes/wave, 4 waves. Thread: nl = t>>4, sub = t&15, owns o = 4sub..4sub+3, all 8 m.
// Accumulators paired over o: acc[p][m] lanes = (o0+2p, o0+2p+1).
template<int CIN>
__global__ void __launch_bounds__(256, 2) k_mlp(
    const float* __restrict__ w1, const float* __restrict__ b1,
    const float* __restrict__ w2, const float* __restrict__ b2)
{
    const int ZROW = CIN*MM + 4;
    const int TROW = HH*MM + 4;

    extern __shared__ float dsm[];
    float* w1s = dsm;                   // [c][o]
    float* w2s = w1s + CIN*HH;          // [c][o]
    float* zs  = w2s + HH*HH;           // [node][c][m]
    float* ts  = zs + 16*ZROW;          // [node][m][o]
    __shared__ __align__(16) float b1s[HH];
    __shared__ __align__(16) float b2s[HH];
    __shared__ float shst[2*HH];

    int tid = threadIdx.x;
    for (int idx = tid; idx < CIN*HH; idx += 256) {
        int o = idx & 63, c = idx >> 6;
        w1s[idx] = w1[o*CIN + c];
    }
    for (int idx = tid; idx < HH*HH; idx += 256) {
        int o = idx & 63, c = idx >> 6;
        w2s[idx] = w2[o*HH + c];
    }
    if (tid < HH)   { b1s[tid] = b1[tid]; b2s[tid] = b2[tid]; }
    if (tid < 2*HH) shst[tid] = 0.f;
    __syncthreads();

    int nl  = tid >> 4;
    int sub = tid & 15;
    int o0  = sub * 4;
    float ssum[4] = {0.f,0.f,0.f,0.f};
    float ssq [4] = {0.f,0.f,0.f,0.f};

    for (int w = 0; w < 4; ++w) {
        int base = blockIdx.x*64 + w*16;
        // ---- stage z tile ----
        const int TOT = 16*CIN*2;
        for (int idx = tid; idx < TOT; idx += 256) {
            int node_l = idx / (CIN*2);
            int r      = idx - node_l*(CIN*2);
            int n      = base + node_l;
            float4 v = make_float4(0.f,0.f,0.f,0.f);
            if (n < NN) v = *(const float4*)&g_z[n*(CIN*MM) + r*4];
            *(float4*)&zs[node_l*ZROW + r*4] = v;
        }
        __syncthreads();

        int n = base + nl;

        // ---- GEMM1 (FFMA2): t[o][m] = relu(b1 + sum_c w1[c][o] z[c][m]) ----
        u64 acc1[2][8];
        {
            ulonglong2 bb = *(const ulonglong2*)&b1s[o0];
            #pragma unroll
            for (int m = 0; m < 8; ++m) { acc1[0][m] = bb.x; acc1[1][m] = bb.y; }
        }
        #pragma unroll 4
        for (int c = 0; c < CIN; ++c) {
            ulonglong2 wp = *(const ulonglong2*)&w1s[c*HH + o0];   // (o0,o0+1),(o0+2,o0+3)
            float4 zl = *(const float4*)&zs[nl*ZROW + c*MM];       // broadcast
            float4 zh = *(const float4*)&zs[nl*ZROW + c*MM + 4];
            u64 zp[8];
            DUP2(zp[0],zl.x); DUP2(zp[1],zl.y); DUP2(zp[2],zl.z); DUP2(zp[3],zl.w);
            DUP2(zp[4],zh.x); DUP2(zp[5],zh.y); DUP2(zp[6],zh.z); DUP2(zp[7],zh.w);
            #pragma unroll
            for (int m = 0; m < 8; ++m) {
                FMA2(acc1[0][m], wp.x, zp[m]);
                FMA2(acc1[1][m], wp.y, zp[m]);
            }
        }
        // relu + write ts in [m][o] (conflict-free float4 over o)
        #pragma unroll
        for (int m = 0; m < 8; ++m) {
            float a,b,c,d;
            UNP2(a,b,acc1[0][m]); UNP2(c,d,acc1[1][m]);
            *(float4*)&ts[nl*TROW + m*HH + o0] =
                make_float4(fmaxf(a,0.f), fmaxf(b,0.f), fmaxf(c,0.f), fmaxf(d,0.f));
        }
        __syncthreads();

        // ---- GEMM2 (FFMA2): u[o][m] = relu(b2 + sum_c w2[c][o] t[c][m]) ----
        u64 acc2[2][8];
        {
            ulonglong2 bb = *(const ulonglong2*)&b2s[o0];
            #pragma unroll
            for (int m = 0; m < 8; ++m) { acc2[0][m] = bb.x; acc2[1][m] = bb.y; }
        }
        for (int c0 = 0; c0 < HH; c0 += 4) {
            float4 t4[8];
            #pragma unroll
            for (int m = 0; m < 8; ++m)
                t4[m] = *(const float4*)&ts[nl*TROW + m*HH + c0];   // broadcast
            #pragma unroll
            for (int jc = 0; jc < 4; ++jc) {
                ulonglong2 wp = *(const ulonglong2*)&w2s[(c0+jc)*HH + o0];
                #pragma unroll
                for (int m = 0; m < 8; ++m) {
                    float tv = (jc==0) ? t4[m].x : (jc==1) ? t4[m].y
                             : (jc==2) ? t4[m].z : t4[m].w;
                    u64 tp; DUP2(tp, tv);
                    FMA2(acc2[0][m], wp.x, tp);
                    FMA2(acc2[1][m], wp.y, tp);
                }
            }
        }
        // ---- epilogue: relu, stats (fp32), store fp16 ----
        if (n < NN) {
            float uo[4][8];
            #pragma unroll
            for (int m = 0; m < 8; ++m) {
                UNP2(uo[0][m], uo[1][m], acc2[0][m]);
                UNP2(uo[2][m], uo[3][m], acc2[1][m]);
            }
            #pragma unroll
            for (int jo = 0; jo < 4; ++jo) {
                #pragma unroll
                for (int m = 0; m < 8; ++m) {
                    float v = fmaxf(uo[jo][m], 0.f);
                    uo[jo][m] = v;
                    ssum[jo] += v;
                    ssq[jo]  += v*v;
                }
                __half2 h0 = __floats2half2_rn(uo[jo][0], uo[jo][1]);
                __half2 h1 = __floats2half2_rn(uo[jo][2], uo[jo][3]);
                __half2 h2 = __floats2half2_rn(uo[jo][4], uo[jo][5]);
                __half2 h3 = __floats2half2_rn(uo[jo][6], uo[jo][7]);
                uint4 pk;
                pk.x = *(unsigned*)&h0; pk.y = *(unsigned*)&h1;
                pk.z = *(unsigned*)&h2; pk.w = *(unsigned*)&h3;
                *(uint4*)&g_uh[n*FEAT + (o0+jo)*MM] = pk;
            }
        }
        __syncthreads();
    }

    #pragma unroll
    for (int jo = 0; jo < 4; ++jo) {
        atomicAdd(&shst[o0+jo],    ssum[jo]);
        atomicAdd(&shst[HH+o0+jo], ssq[jo]);
    }
    __syncthreads();
    if (tid < 2*HH) atomicAdd(&g_stats[tid], shst[tid]);
}

// ---------------- BN params (also resets stats) ----------------
__global__ void k_bnparams(const float* __restrict__ gamma,
                           const float* __restrict__ beta) {
    int c = threadIdx.x;
    if (c < HH) {
        float s  = g_stats[c];
        float ss = g_stats[HH + c];
        g_stats[c] = 0.f;
        g_stats[HH + c] = 0.f;
        float mean = s * NMINV;
        float var  = ss * NMINV - mean*mean;
        float r  = rsqrtf(var + BN_EPS);
        float sc = gamma[c] * r;
        g_scale[c] = sc;
        g_shift[c] = beta[c] - mean*sc;
    }
}

// ---------------- pooling + head ----------------
__global__ void k_pool() {
    int cm = threadIdx.x;                // 512 threads: one (c,m)
    int nb = blockIdx.x * 128;
    int ne = min(nb + 128, NN);
    float acc = 0.f;
    for (int n = nb; n < ne; ++n) acc += __half2float(g_uh[n*FEAT + cm]);
    atomicAdd(&g_pool[cm], acc);
}

__global__ void k_out(const float* __restrict__ w_out,
                      const float* __restrict__ b_out,
                      float* __restrict__ out) {
    int m = threadIdx.x;
    if (m < MM) {
        float acc = 0.f;
        for (int h = 0; h < HH; ++h) {
            float ph = fmaf(g_scale[h], g_pool[h*MM + m] / (float)NN, g_shift[h]);
            acc += w_out[h] * ph;
        }
        float v = acc + b_out[0];
        out[m] = 1.f / (1.f + expf(-v));
    }
}

// ---------------- launch ----------------
extern "C" void kernel_launch(void* const* d_in, const int* in_sizes, int n_in,
                              void* d_out, int out_size) {
    const float* x     = (const float*)d_in[0];
    const int*   ei    = (const int*)d_in[1];
    const float* w1_0  = (const float*)d_in[3];
    const float* w1    = (const float*)d_in[4];
    const float* b1    = (const float*)d_in[5];
    const float* w2    = (const float*)d_in[6];
    const float* b2    = (const float*)d_in[7];
    const float* gamma = (const float*)d_in[8];
    const float* beta  = (const float*)d_in[9];
    const float* w_out = (const float*)d_in[10];
    const float* b_out = (const float*)d_in[11];
    float*       out   = (float*)d_out;

    const int SM1  = (1*HH  + HH*HH + 16*(1*MM+4)  + 16*(HH*MM+4)) * 4;
    const int SM64 = (HH*HH + HH*HH + 16*(HH*MM+4) + 16*(HH*MM+4)) * 4;
    cudaFuncSetAttribute(k_mlp<1>,  cudaFuncAttributeMaxDynamicSharedMemorySize, SM1);
    cudaFuncSetAttribute(k_mlp<HH>, cudaFuncAttributeMaxDynamicSharedMemorySize, SM64);

    // CSR build
    k_zero_init<<<(NN + 255)/256, 256>>>();
    k_hist<<<(EE + 255)/256, 256>>>(ei);
    k_scan<<<1, 1024>>>();
    k_fill<<<(EE + 255)/256, 256>>>(ei);

    const int MLPG = (NN + 63)/64;

    // layer 0 (cin = 1)
    k_agg0<<<(NN + 255)/256, 256>>>(x);
    k_mlp<1><<<MLPG, 256, SM1>>>(w1_0, b1, w2, b2);
    k_bnparams<<<1, 64>>>(gamma, beta);

    // layers 1..4
    for (int i = 1; i < 5; ++i) {
        k_aggbn<<<NN, 128>>>();
        k_mlp<HH><<<MLPG, 256, SM64>>>(w1 + (i-1)*HH*HH, b1 + i*HH,
                                       w2 + i*HH*HH,     b2 + i*HH);
        k_bnparams<<<1, 64>>>(gamma + i*HH, beta + i*HH);
    }

    k_pool<<<(NN + 127)/128, 512>>>();
    k_out<<<1, 32>>>(w_out, b_out, out);
}

// round 7
// speedup vs baseline: 1.6608x; 1.0423x over previous
#include <cuda_runtime.h>
#include <cuda_fp16.h>
#include <math.h>

#define NN 20000
#define EE 320000
#define HH 64
#define MM 8
#define FEAT (HH*MM)
#define NMINV (1.0f/(float)(NN*MM))
#define BN_EPS 1e-5f

typedef unsigned long long u64;

// packed fp32x2 (Blackwell FFMA2)
#define FMA2(d,a,b)   asm("fma.rn.f32x2 %0,%1,%2,%0;" : "+l"(d) : "l"(a), "l"(b))
#define DUP2(d,s)     asm("mov.b64 %0,{%1,%1};"       : "=l"(d) : "f"(s))
#define UNP2(lo,hi,s) asm("mov.b64 {%0,%1},%2;" : "=f"(lo), "=f"(hi) : "l"(s))
// async copy global->shared (LDGSTS)
#define CP16(dst,src) asm volatile("cp.async.cg.shared.global [%0], [%1], 16;" \
                        :: "r"((unsigned)__cvta_generic_to_shared(dst)), "l"(src))
#define CP_COMMIT()   asm volatile("cp.async.commit_group;")
#define CP_WAIT0()    asm volatile("cp.async.wait_group 0;" ::: "memory")

// ---------------- scratch ----------------
__device__ __align__(128) float  g_z[NN*FEAT];
__device__ __align__(128) __half g_uh[NN*FEAT];
__device__ __align__(128) int    g_rowptr[NN+1];
__device__ __align__(128) int    g_cnt[NN];
__device__ __align__(128) int    g_col[EE];
__device__ __align__(128) float  g_stats[5*2*HH];   // per-layer sum/sumsq slots
__device__ __align__(128) float  g_pool[FEAT];

// ---------------- CSR build ----------------
__global__ void k_zero_init() {
    int i = blockIdx.x*blockDim.x + threadIdx.x;
    if (i < NN)      g_cnt[i] = 0;
    if (i < FEAT)    g_pool[i] = 0.f;
    if (i < 5*2*HH)  g_stats[i] = 0.f;
}

__global__ void k_hist(const int* __restrict__ ei) {
    int e = blockIdx.x*blockDim.x + threadIdx.x;
    if (e < EE) atomicAdd(&g_cnt[ei[EE + e]], 1);
}

__global__ void k_scan() {
    __shared__ int sh[1024];
    const int PER = (NN + 1023) / 1024;
    int tid = threadIdx.x;
    int base = tid * PER;
    int s = 0;
    for (int i = 0; i < PER; ++i) {
        int idx = base + i;
        if (idx < NN) s += g_cnt[idx];
    }
    sh[tid] = s;
    __syncthreads();
    for (int off = 1; off < 1024; off <<= 1) {
        int t = 0;
        if (tid >= off) t = sh[tid - off];
        __syncthreads();
        sh[tid] += t;
        __syncthreads();
    }
    int run = sh[tid] - s;
    for (int i = 0; i < PER; ++i) {
        int idx = base + i;
        if (idx < NN) {
            int c = g_cnt[idx];
            g_rowptr[idx] = run;
            run += c;
            g_cnt[idx] = 0;
        }
    }
    if (tid == 1023) g_rowptr[NN] = sh[1023];
}

__global__ void k_fill(const int* __restrict__ ei) {
    int e = blockIdx.x*blockDim.x + threadIdx.x;
    if (e < EE) {
        int d = ei[EE + e];
        int pos = g_rowptr[d] + atomicAdd(&g_cnt[d], 1);
        g_col[pos] = ei[e];
    }
}

// ---------------- fused BN + aggregation (layers 1..4) ----------------
// z = scale_c * (u_self + sum u_nbr) + (deg+1) * shift_c ; BN params from stats slot
__global__ void k_aggbn(int slot, const float* __restrict__ gamma,
                        const float* __restrict__ beta) {
    int n  = blockIdx.x;
    int t  = threadIdx.x;          // 128 threads x 4 halves
    int h4 = t * 4;
    int c  = t >> 1;
    // inline BN params (deterministic, redundant per block)
    float sm = g_stats[slot*2*HH + c];
    float sq = g_stats[slot*2*HH + HH + c];
    float mean = sm * NMINV;
    float var  = sq * NMINV - mean*mean;
    float r  = rsqrtf(var + BN_EPS);
    float sc = gamma[c] * r;
    float sh = beta[c] - mean*sc;

    float4 a, b = make_float4(0.f,0.f,0.f,0.f);
    {
        uint2 rr = *(const uint2*)&g_uh[n*FEAT + h4];
        float2 f0 = __half22float2(*(__half2*)&rr.x);
        float2 f1 = __half22float2(*(__half2*)&rr.y);
        a = make_float4(f0.x, f0.y, f1.x, f1.y);
    }
    int beg = g_rowptr[n], end = g_rowptr[n+1];
    int j = beg;
    for (; j + 1 < end; j += 2) {
        int s0 = g_col[j], s1 = g_col[j+1];
        uint2 r0 = *(const uint2*)&g_uh[s0*FEAT + h4];
        uint2 r1 = *(const uint2*)&g_uh[s1*FEAT + h4];
        float2 p0 = __half22float2(*(__half2*)&r0.x);
        float2 p1 = __half22float2(*(__half2*)&r0.y);
        float2 q0 = __half22float2(*(__half2*)&r1.x);
        float2 q1 = __half22float2(*(__half2*)&r1.y);
        a.x += p0.x; a.y += p0.y; a.z += p1.x; a.w += p1.y;
        b.x += q0.x; b.y += q0.y; b.z += q1.x; b.w += q1.y;
    }
    if (j < end) {
        int s0 = g_col[j];
        uint2 r0 = *(const uint2*)&g_uh[s0*FEAT + h4];
        float2 p0 = __half22float2(*(__half2*)&r0.x);
        float2 p1 = __half22float2(*(__half2*)&r0.y);
        a.x += p0.x; a.y += p0.y; a.z += p1.x; a.w += p1.y;
    }
    float cnt = (float)(end - beg + 1);
    float add = cnt * sh;
    a.x = fmaf(sc, a.x + b.x, add);
    a.y = fmaf(sc, a.y + b.y, add);
    a.z = fmaf(sc, a.z + b.z, add);
    a.w = fmaf(sc, a.w + b.w, add);
    *(float4*)&g_z[n*FEAT + h4] = a;
}

// ---------------- MLP: FFMA2 double GEMM + relu + BN stats ----------------
// 256 threads, 16 nodes/wave, 4 waves. nl = t>>4, sub = t&15, o = 4sub..4sub+3, 8 m.
// CIN==1 fuses the layer-0 aggregation (gather from x) into staging.
template<int CIN>
__global__ void __launch_bounds__(256, 2) k_mlp(
    const float* __restrict__ x,
    const float* __restrict__ w1, const float* __restrict__ b1,
    const float* __restrict__ w2, const float* __restrict__ b2,
    int slot)
{
    const int ZROW = CIN*MM + 4;
    const int TROW = HH*MM + 4;

    extern __shared__ float dsm[];
    float* w1s = dsm;                   // [c][o]
    float* w2s = w1s + CIN*HH;          // [c][o]
    float* zs  = w2s + HH*HH;           // [node][c][m]
    float* ts  = zs + 16*ZROW;          // [node][m][o]
    __shared__ __align__(16) float b1s[HH];
    __shared__ __align__(16) float b2s[HH];
    __shared__ float shst[2*HH];

    int tid = threadIdx.x;
    for (int idx = tid; idx < CIN*HH; idx += 256) {
        int o = idx & 63, c = idx >> 6;
        w1s[idx] = w1[o*CIN + c];
    }
    for (int idx = tid; idx < HH*HH; idx += 256) {
        int o = idx & 63, c = idx >> 6;
        w2s[idx] = w2[o*HH + c];
    }
    if (tid < HH)   { b1s[tid] = b1[tid]; b2s[tid] = b2[tid]; }
    if (tid < 2*HH) shst[tid] = 0.f;

    // ---- stage wave 0 ----
    if (CIN == 64) {
        int base = blockIdx.x*64;
        const int TOT = 16*CIN*2;
        for (int idx = tid; idx < TOT; idx += 256) {
            int node_l = idx / (CIN*2);
            int r      = idx - node_l*(CIN*2);
            int n      = base + node_l;
            float* dst = &zs[node_l*ZROW + r*4];
            if (n < NN) CP16(dst, &g_z[n*(CIN*MM) + r*4]);
            else        *(float4*)dst = make_float4(0.f,0.f,0.f,0.f);
        }
        CP_COMMIT(); CP_WAIT0();
    } else if (tid < 128) {
        // fused layer-0 aggregation: z[n][m] = x[n][m] + sum_nbr x[s][m]
        int nl = tid >> 3, m = tid & 7;
        int n  = blockIdx.x*64 + nl;
        float a = 0.f;
        if (n < NN) {
            a = x[n*MM + m];
            int beg = g_rowptr[n], end = g_rowptr[n+1];
            for (int j = beg; j < end; ++j) a += x[g_col[j]*MM + m];
        }
        zs[nl*ZROW + m] = a;
    }
    __syncthreads();

    int nl  = tid >> 4;
    int sub = tid & 15;
    int o0  = sub * 4;
    float ssum[4] = {0.f,0.f,0.f,0.f};
    float ssq [4] = {0.f,0.f,0.f,0.f};

    for (int w = 0; w < 4; ++w) {
        int base = blockIdx.x*64 + w*16;
        int n = base + nl;

        // ---- GEMM1 (FFMA2): t[o][m] = relu(b1 + sum_c w1[c][o] z[c][m]) ----
        u64 acc1[2][8];
        {
            ulonglong2 bb = *(const ulonglong2*)&b1s[o0];
            #pragma unroll
            for (int m = 0; m < 8; ++m) { acc1[0][m] = bb.x; acc1[1][m] = bb.y; }
        }
        #pragma unroll 4
        for (int c = 0; c < CIN; ++c) {
            ulonglong2 wp = *(const ulonglong2*)&w1s[c*HH + o0];
            float4 zl = *(const float4*)&zs[nl*ZROW + c*MM];
            float4 zh = *(const float4*)&zs[nl*ZROW + c*MM + 4];
            u64 zp[8];
            DUP2(zp[0],zl.x); DUP2(zp[1],zl.y); DUP2(zp[2],zl.z); DUP2(zp[3],zl.w);
            DUP2(zp[4],zh.x); DUP2(zp[5],zh.y); DUP2(zp[6],zh.z); DUP2(zp[7],zh.w);
            #pragma unroll
            for (int m = 0; m < 8; ++m) {
                FMA2(acc1[0][m], wp.x, zp[m]);
                FMA2(acc1[1][m], wp.y, zp[m]);
            }
        }
        #pragma unroll
        for (int m = 0; m < 8; ++m) {
            float a,b,c,d;
            UNP2(a,b,acc1[0][m]); UNP2(c,d,acc1[1][m]);
            *(float4*)&ts[nl*TROW + m*HH + o0] =
                make_float4(fmaxf(a,0.f), fmaxf(b,0.f), fmaxf(c,0.f), fmaxf(d,0.f));
        }
        __syncthreads();   // ts written; zs free

        // ---- stage wave w+1 (hidden behind GEMM2) ----
        if (w < 3) {
            int nbase = blockIdx.x*64 + (w+1)*16;
            if (CIN == 64) {
                const int TOT = 16*CIN*2;
                for (int idx = tid; idx < TOT; idx += 256) {
                    int node_l = idx / (CIN*2);
                    int r      = idx - node_l*(CIN*2);
                    int nn     = nbase + node_l;
                    float* dst = &zs[node_l*ZROW + r*4];
                    if (nn < NN) CP16(dst, &g_z[nn*(CIN*MM) + r*4]);
                    else         *(float4*)dst = make_float4(0.f,0.f,0.f,0.f);
                }
                CP_COMMIT();
            } else if (tid < 128) {
                int nl2 = tid >> 3, m = tid & 7;
                int nn  = nbase + nl2;
                float a = 0.f;
                if (nn < NN) {
                    a = x[nn*MM + m];
                    int beg = g_rowptr[nn], end = g_rowptr[nn+1];
                    for (int j = beg; j < end; ++j) a += x[g_col[j]*MM + m];
                }
                zs[nl2*ZROW + m] = a;
            }
        }

        // ---- GEMM2 (FFMA2): u[o][m] = relu(b2 + sum_c w2[c][o] t[c][m]) ----
        u64 acc2[2][8];
        {
            ulonglong2 bb = *(const ulonglong2*)&b2s[o0];
            #pragma unroll
            for (int m = 0; m < 8; ++m) { acc2[0][m] = bb.x; acc2[1][m] = bb.y; }
        }
        for (int c0 = 0; c0 < HH; c0 += 4) {
            float4 t4[8];
            #pragma unroll
            for (int m = 0; m < 8; ++m)
                t4[m] = *(const float4*)&ts[nl*TROW + m*HH + c0];
            #pragma unroll
            for (int jc = 0; jc < 4; ++jc) {
                ulonglong2 wp = *(const ulonglong2*)&w2s[(c0+jc)*HH + o0];
                #pragma unroll
                for (int m = 0; m < 8; ++m) {
                    float tv = (jc==0) ? t4[m].x : (jc==1) ? t4[m].y
                             : (jc==2) ? t4[m].z : t4[m].w;
                    u64 tp; DUP2(tp, tv);
                    FMA2(acc2[0][m], wp.x, tp);
                    FMA2(acc2[1][m], wp.y, tp);
                }
            }
        }
        // ---- epilogue: relu, stats (fp32), fp16 store ----
        if (n < NN) {
            float uo[4][8];
            #pragma unroll
            for (int m = 0; m < 8; ++m) {
                UNP2(uo[0][m], uo[1][m], acc2[0][m]);
                UNP2(uo[2][m], uo[3][m], acc2[1][m]);
            }
            #pragma unroll
            for (int jo = 0; jo < 4; ++jo) {
                #pragma unroll
                for (int m = 0; m < 8; ++m) {
                    float v = fmaxf(uo[jo][m], 0.f);
                    uo[jo][m] = v;
                    ssum[jo] += v;
                    ssq[jo]  += v*v;
                }
                __half2 h0 = __floats2half2_rn(uo[jo][0], uo[jo][1]);
                __half2 h1 = __floats2half2_rn(uo[jo][2], uo[jo][3]);
                __half2 h2 = __floats2half2_rn(uo[jo][4], uo[jo][5]);
                __half2 h3 = __floats2half2_rn(uo[jo][6], uo[jo][7]);
                uint4 pk;
                pk.x = *(unsigned*)&h0; pk.y = *(unsigned*)&h1;
                pk.z = *(unsigned*)&h2; pk.w = *(unsigned*)&h3;
                *(uint4*)&g_uh[n*FEAT + (o0+jo)*MM] = pk;
            }
        }
        if (CIN == 64) CP_WAIT0();
        __syncthreads();   // ts free; zs(w+1) visible
    }

    #pragma unroll
    for (int jo = 0; jo < 4; ++jo) {
        atomicAdd(&shst[o0+jo],    ssum[jo]);
        atomicAdd(&shst[HH+o0+jo], ssq[jo]);
    }
    __syncthreads();
    if (tid < 2*HH) atomicAdd(&g_stats[slot*2*HH + tid], shst[tid]);
}

// ---------------- pooling + head ----------------
__global__ void k_pool() {
    int cm = threadIdx.x;
    int nb = blockIdx.x * 128;
    int ne = min(nb + 128, NN);
    float acc = 0.f;
    for (int n = nb; n < ne; ++n) acc += __half2float(g_uh[n*FEAT + cm]);
    atomicAdd(&g_pool[cm], acc);
}

__global__ void k_out(const float* __restrict__ gamma4,
                      const float* __restrict__ beta4,
                      const float* __restrict__ w_out,
                      const float* __restrict__ b_out,
                      float* __restrict__ out) {
    int m = threadIdx.x;
    if (m < MM) {
        float acc = 0.f;
        for (int h = 0; h < HH; ++h) {
            float sm = g_stats[4*2*HH + h];
            float sq = g_stats[4*2*HH + HH + h];
            float mean = sm * NMINV;
            float var  = sq * NMINV - mean*mean;
            float r  = rsqrtf(var + BN_EPS);
            float sc = gamma4[h] * r;
            float sh = beta4[h] - mean*sc;
            float ph = fmaf(sc, g_pool[h*MM + m] / (float)NN, sh);
            acc += w_out[h] * ph;
        }
        float v = acc + b_out[0];
        out[m] = 1.f / (1.f + expf(-v));
    }
}

// ---------------- launch ----------------
extern "C" void kernel_launch(void* const* d_in, const int* in_sizes, int n_in,
                              void* d_out, int out_size) {
    const float* x     = (const float*)d_in[0];
    const int*   ei    = (const int*)d_in[1];
    const float* w1_0  = (const float*)d_in[3];
    const float* w1    = (const float*)d_in[4];
    const float* b1    = (const float*)d_in[5];
    const float* w2    = (const float*)d_in[6];
    const float* b2    = (const float*)d_in[7];
    const float* gamma = (const float*)d_in[8];
    const float* beta  = (const float*)d_in[9];
    const float* w_out = (const float*)d_in[10];
    const float* b_out = (const float*)d_in[11];
    float*       out   = (float*)d_out;

    const int SM1  = (1*HH  + HH*HH + 16*(1*MM+4)  + 16*(HH*MM+4)) * 4;
    const int SM64 = (HH*HH + HH*HH + 16*(HH*MM+4) + 16*(HH*MM+4)) * 4;
    cudaFuncSetAttribute(k_mlp<1>,  cudaFuncAttributeMaxDynamicSharedMemorySize, SM1);
    cudaFuncSetAttribute(k_mlp<HH>, cudaFuncAttributeMaxDynamicSharedMemorySize, SM64);

    // CSR build
    k_zero_init<<<(NN + 255)/256, 256>>>();
    k_hist<<<(EE + 255)/256, 256>>>(ei);
    k_scan<<<1, 1024>>>();
    k_fill<<<(EE + 255)/256, 256>>>(ei);

    const int MLPG = (NN + 63)/64;

    // layer 0 (aggregation fused into staging)
    k_mlp<1><<<MLPG, 256, SM1>>>(x, w1_0, b1, w2, b2, 0);

    // layers 1..4
    for (int i = 1; i < 5; ++i) {
        k_aggbn<<<NN, 128>>>(i-1, gamma + (i-1)*HH, beta + (i-1)*HH);
        k_mlp<HH><<<MLPG, 256, SM64>>>(nullptr, w1 + (i-1)*HH*HH, b1 + i*HH,
                                       w2 + i*HH*HH, b2 + i*HH, i);
    }

    k_pool<<<(NN + 127)/128, 512>>>();
    k_out<<<1, 32>>>(gamma + 4*HH, beta + 4*HH, w_out, b_out, out);
}

// round 11
// speedup vs baseline: 2.9254x; 1.7615x over previous
#include <cuda_runtime.h>
#include <cuda_fp16.h>
#include <math.h>

#define NN 20000
#define EE 320000
#define HH 64
#define MM 8
#define FEAT 512
#define NMINV (1.0f/160000.0f)
#define BN_EPS 1e-5f
#define NTILES 1250          // 160000 rows / 128
#define ROWP 72              // padded smem row (halves) = 144 B
#define DSMEM 55296          // 2*9216 (W) + 2*18432 (Z,T)

typedef unsigned long long u64;
typedef unsigned int u32;

// ---------------- scratch ----------------
__device__ __align__(128) __half g_zh[NN*FEAT];   // MLP input  [row=(n,m)][c] fp16
__device__ __align__(128) __half g_uh[NN*FEAT];   // MLP output [row=(n,m)][c] fp16
__device__ __align__(128) int    g_rowptr[NN+1];
__device__ __align__(128) int    g_cnt[NN];
__device__ __align__(128) int    g_col[EE];
__device__ __align__(128) float  g_stats[5*2*HH];
__device__ __align__(128) float  g_pool[FEAT];

__device__ __forceinline__ u32 smem_u32(const void* p) {
    u32 a;
    asm("{ .reg .u64 t; cvta.to.shared.u64 t, %1; cvt.u32.u64 %0, t; }" : "=r"(a) : "l"(p));
    return a;
}
#define CP16(dst_u32,src) asm volatile("cp.async.cg.shared.global [%0], [%1], 16;" :: "r"(dst_u32), "l"(src))
#define CP_COMMIT()  asm volatile("cp.async.commit_group;")
#define CP_WAIT0()   asm volatile("cp.async.wait_group 0;" ::: "memory")

#define LDSM4(r0,r1,r2,r3,a) \
    asm volatile("ldmatrix.sync.aligned.m8n8.x4.shared.b16 {%0,%1,%2,%3}, [%4];" \
        : "=r"(r0),"=r"(r1),"=r"(r2),"=r"(r3) : "r"(a))
#define LDSM2(r0,r1,a) \
    asm volatile("ldmatrix.sync.aligned.m8n8.x2.shared.b16 {%0,%1}, [%2];" \
        : "=r"(r0),"=r"(r1) : "r"(a))
#define MMA16816(c,a0,a1,a2,a3,b0,b1) \
    asm volatile("mma.sync.aligned.m16n8k16.row.col.f32.f16.f16.f32 " \
        "{%0,%1,%2,%3}, {%4,%5,%6,%7}, {%8,%9}, {%0,%1,%2,%3};" \
        : "+f"((c)[0]),"+f"((c)[1]),"+f"((c)[2]),"+f"((c)[3]) \
        : "r"(a0),"r"(a1),"r"(a2),"r"(a3),"r"(b0),"r"(b1))

// ---------------- CSR build ----------------
__global__ void k_zero_init() {
    int i = blockIdx.x*blockDim.x + threadIdx.x;
    if (i < NN)      g_cnt[i] = 0;
    if (i < FEAT)    g_pool[i] = 0.f;
    if (i < 5*2*HH)  g_stats[i] = 0.f;
}
__global__ void k_hist(const int* __restrict__ ei) {
    int e = blockIdx.x*blockDim.x + threadIdx.x;
    if (e < EE) atomicAdd(&g_cnt[ei[EE + e]], 1);
}
__global__ void k_scan() {
    __shared__ int sh[1024];
    const int PER = (NN + 1023) / 1024;
    int tid = threadIdx.x;
    int base = tid * PER;
    int s = 0;
    for (int i = 0; i < PER; ++i) { int idx = base + i; if (idx < NN) s += g_cnt[idx]; }
    sh[tid] = s;
    __syncthreads();
    for (int off = 1; off < 1024; off <<= 1) {
        int t = 0;
        if (tid >= off) t = sh[tid - off];
        __syncthreads();
        sh[tid] += t;
        __syncthreads();
    }
    int run = sh[tid] - s;
    for (int i = 0; i < PER; ++i) {
        int idx = base + i;
        if (idx < NN) { int c = g_cnt[idx]; g_rowptr[idx] = run; run += c; g_cnt[idx] = 0; }
    }
    if (tid == 1023) g_rowptr[NN] = sh[1023];
}
__global__ void k_fill(const int* __restrict__ ei) {
    int e = blockIdx.x*blockDim.x + threadIdx.x;
    if (e < EE) {
        int d = ei[EE + e];
        int pos = g_rowptr[d] + atomicAdd(&g_cnt[d], 1);
        g_col[pos] = ei[e];
    }
}

// ---------------- fused BN + aggregation (layers 1..4) ----------------
__global__ void k_aggbn(int slot, const float* __restrict__ gamma,
                        const float* __restrict__ beta) {
    __shared__ float scs[HH], shs[HH];
    int n = blockIdx.x, t = threadIdx.x;
    if (t < HH) {
        float sm = g_stats[slot*2*HH + t];
        float sq = g_stats[slot*2*HH + HH + t];
        float mean = sm * NMINV;
        float var  = sq * NMINV - mean*mean;
        float r  = rsqrtf(var + BN_EPS);
        float sc = gamma[t] * r;
        scs[t] = sc;
        shs[t] = beta[t] - mean*sc;
    }
    __syncthreads();
    int h4 = t*4;
    int c0 = h4 & 63;
    float4 a, b = make_float4(0.f,0.f,0.f,0.f);
    {
        uint2 rr = *(const uint2*)&g_uh[n*FEAT + h4];
        float2 f0 = __half22float2(*(__half2*)&rr.x);
        float2 f1 = __half22float2(*(__half2*)&rr.y);
        a = make_float4(f0.x, f0.y, f1.x, f1.y);
    }
    int beg = g_rowptr[n], end = g_rowptr[n+1];
    int j = beg;
    for (; j + 1 < end; j += 2) {
        int s0 = g_col[j], s1 = g_col[j+1];
        uint2 r0 = *(const uint2*)&g_uh[s0*FEAT + h4];
        uint2 r1 = *(const uint2*)&g_uh[s1*FEAT + h4];
        float2 p0 = __half22float2(*(__half2*)&r0.x);
        float2 p1 = __half22float2(*(__half2*)&r0.y);
        float2 q0 = __half22float2(*(__half2*)&r1.x);
        float2 q1 = __half22float2(*(__half2*)&r1.y);
        a.x += p0.x; a.y += p0.y; a.z += p1.x; a.w += p1.y;
        b.x += q0.x; b.y += q0.y; b.z += q1.x; b.w += q1.y;
    }
    if (j < end) {
        int s0 = g_col[j];
        uint2 r0 = *(const uint2*)&g_uh[s0*FEAT + h4];
        float2 p0 = __half22float2(*(__half2*)&r0.x);
        float2 p1 = __half22float2(*(__half2*)&r0.y);
        a.x += p0.x; a.y += p0.y; a.z += p1.x; a.w += p1.y;
    }
    float cnt = (float)(end - beg + 1);
    float z0 = fmaf(scs[c0],   a.x + b.x, cnt*shs[c0]);
    float z1 = fmaf(scs[c0+1], a.y + b.y, cnt*shs[c0+1]);
    float z2 = fmaf(scs[c0+2], a.z + b.z, cnt*shs[c0+2]);
    float z3 = fmaf(scs[c0+3], a.w + b.w, cnt*shs[c0+3]);
    __half2 h0 = __floats2half2_rn(z0, z1);
    __half2 h1 = __floats2half2_rn(z2, z3);
    uint2 pk; pk.x = *(u32*)&h0; pk.y = *(u32*)&h1;
    *(uint2*)&g_zh[n*FEAT + h4] = pk;
}

// ---------------- warp GEMM: D[128x64] = A[128x64] * W[64x64]^T ----------------
// A fp16 smem rows padded ROWP halves; W fp16 smem [o][c] rows padded ROWP.
// acc[mt][nt][4]; warp wid owns rows 32*wid .. +31.
__device__ __forceinline__ void warp_gemm(u32 abase, u32 bbase, float acc[2][8][4],
                                          int lane, int wid) {
    #pragma unroll
    for (int mt = 0; mt < 2; ++mt)
        #pragma unroll
        for (int nt = 0; nt < 8; ++nt)
            #pragma unroll
            for (int q = 0; q < 4; ++q) acc[mt][nt][q] = 0.f;

    int seg = lane >> 3, lr = lane & 7;
    int l8  = lane & 7, bhalf = (lane >> 3) & 1;
    #pragma unroll
    for (int k = 0; k < 4; ++k) {
        u32 a[2][4];
        #pragma unroll
        for (int mt = 0; mt < 2; ++mt) {
            int row = wid*32 + mt*16 + (seg & 1)*8 + lr;
            int col = k*16 + (seg >> 1)*8;
            u32 addr = abase + (u32)(row*(ROWP*2) + col*2);
            LDSM4(a[mt][0], a[mt][1], a[mt][2], a[mt][3], addr);
        }
        #pragma unroll
        for (int nt = 0; nt < 8; ++nt) {
            int brow = nt*8 + l8;
            int bcol = k*16 + bhalf*8;
            u32 baddr = bbase + (u32)(brow*(ROWP*2) + bcol*2);
            u32 b0, b1;
            LDSM2(b0, b1, baddr);
            MMA16816(acc[0][nt], a[0][0], a[0][1], a[0][2], a[0][3], b0, b1);
            MMA16816(acc[1][nt], a[1][0], a[1][1], a[1][2], a[1][3], b0, b1);
        }
    }
}

// epilogue: relu(acc + bias[c]) -> fp16 smem [row][c] (padded ROWP)
__device__ __forceinline__ void warp_epi(__half* dst, const float* bias,
                                         float acc[2][8][4], int lane, int wid) {
    int g = lane >> 2, t2 = (lane & 3)*2;
    #pragma unroll
    for (int mt = 0; mt < 2; ++mt) {
        int r = wid*32 + mt*16 + g;
        #pragma unroll
        for (int nt = 0; nt < 8; ++nt) {
            int c = nt*8 + t2;
            float b0 = bias[c], b1 = bias[c+1];
            __half2 h0 = __floats2half2_rn(fmaxf(acc[mt][nt][0]+b0, 0.f),
                                           fmaxf(acc[mt][nt][1]+b1, 0.f));
            __half2 h1 = __floats2half2_rn(fmaxf(acc[mt][nt][2]+b0, 0.f),
                                           fmaxf(acc[mt][nt][3]+b1, 0.f));
            *(__half2*)&dst[r*ROWP + c]     = h0;
            *(__half2*)&dst[(r+8)*ROWP + c] = h1;
        }
    }
}

// ---------------- MLP: tensor-core (mma.sync) double GEMM ----------------
template<int CIN>
__global__ void __launch_bounds__(128) k_mlp_mma(
    const float* __restrict__ x,
    const float* __restrict__ w1p, const float* __restrict__ b1p,
    const float* __restrict__ w2p, const float* __restrict__ b2p,
    int slot)
{
    extern __shared__ __align__(16) char dsm[];
    __half* W1s = (__half*)dsm;                 // [64][ROWP]
    __half* W2s = (__half*)(dsm + 9216);        // [64][ROWP]
    __half* Zs  = (__half*)(dsm + 18432);       // [128][ROWP]
    __half* Ts  = (__half*)(dsm + 36864);       // [128][ROWP]
    __shared__ float b1s[HH], b2s[HH], w1f[HH];
    __shared__ float shst[2*HH];

    int tid  = threadIdx.x;
    int wid  = tid >> 5;
    int lane = tid & 31;
    int tile = blockIdx.x;

    // weights -> smem fp16
    for (int idx = tid; idx < HH*HH; idx += 128) {
        int o = idx >> 6, c = idx & 63;
        if (CIN == 64) W1s[o*ROWP + c] = __float2half(w1p[o*HH + c]);
        W2s[o*ROWP + c] = __float2half(w2p[o*HH + c]);
    }
    if (tid < HH) {
        b1s[tid] = b1p[tid];
        b2s[tid] = b2p[tid];
        if (CIN == 1) w1f[tid] = w1p[tid];
    }
    if (tid < 2*HH) shst[tid] = 0.f;

    // ---- staging ----
    if (CIN == 64) {
        const __half* src = g_zh + (size_t)tile*8192;
        u32 zb = smem_u32(Zs);
        #pragma unroll
        for (int i = 0; i < 8; ++i) {
            int idx = i*128 + tid;
            int row = idx >> 3, ch = idx & 7;
            CP16(zb + (u32)(row*(ROWP*2) + ch*16), src + row*64 + ch*8);
        }
        CP_COMMIT(); CP_WAIT0();
    } else {
        // layer 0: t_row = relu(b1 + w1_0 * z_row), z from fused aggregation
        int gr = tile*128 + tid;
        int n = gr >> 3, m = gr & 7;
        float z = x[n*MM + m];
        int beg = g_rowptr[n], end = g_rowptr[n+1];
        for (int j = beg; j < end; ++j) z += x[g_col[j]*MM + m];
        __syncthreads();   // w1f/b1s ready
        #pragma unroll
        for (int w = 0; w < 32; ++w) {
            float v0 = fmaxf(fmaf(w1f[2*w],   z, b1s[2*w]),   0.f);
            float v1 = fmaxf(fmaf(w1f[2*w+1], z, b1s[2*w+1]), 0.f);
            *(__half2*)&Ts[tid*ROWP + 2*w] = __floats2half2_rn(v0, v1);
        }
    }
    __syncthreads();

    u32 zbase  = smem_u32(Zs);
    u32 tbase  = smem_u32(Ts);
    u32 w1base = smem_u32(W1s);
    u32 w2base = smem_u32(W2s);

    float acc[2][8][4];
    if (CIN == 64) {
        warp_gemm(zbase, w1base, acc, lane, wid);
        warp_epi(Ts, b1s, acc, lane, wid);
        __syncwarp();      // own-warp rows only: warp-visibility is enough
    }
    warp_gemm(tbase, w2base, acc, lane, wid);
    warp_epi(Zs, b2s, acc, lane, wid);   // reuse Zs as output staging
    __syncthreads();

    // ---- copy to g_uh (uint4) + fused BN stats ----
    {
        float s[8] = {0,0,0,0,0,0,0,0}, q[8] = {0,0,0,0,0,0,0,0};
        int c0 = (tid & 7) * 8;
        __half* ubase = g_uh + (size_t)tile*8192;
        #pragma unroll
        for (int i = 0; i < 8; ++i) {
            int idx = i*128 + tid;
            int row = idx >> 3;
            uint4 v = *(uint4*)&Zs[row*ROWP + c0];
            *(uint4*)&ubase[row*64 + c0] = v;
            u32 pk[4] = {v.x, v.y, v.z, v.w};
            #pragma unroll
            for (int p = 0; p < 4; ++p) {
                float2 f = __half22float2(*(__half2*)&pk[p]);
                s[2*p]   += f.x; q[2*p]   += f.x*f.x;
                s[2*p+1] += f.y; q[2*p+1] += f.y*f.y;
            }
        }
        #pragma unroll
        for (int j = 0; j < 8; ++j) {
            atomicAdd(&shst[c0+j],      s[j]);
            atomicAdd(&shst[HH+c0+j],   q[j]);
        }
    }
    __syncthreads();
    if (tid < 2*HH) atomicAdd(&g_stats[slot*2*HH + tid], shst[tid]);
}

// ---------------- pooling + head ----------------
__global__ void k_pool() {
    int cm = threadIdx.x;                 // (m*64 + c)
    int nb = blockIdx.x * 128;
    int ne = min(nb + 128, NN);
    float acc = 0.f;
    for (int n = nb; n < ne; ++n) acc += __half2float(g_uh[n*FEAT + cm]);
    atomicAdd(&g_pool[cm], acc);
}

__global__ void k_out(const float* __restrict__ gamma4,
                      const float* __restrict__ beta4,
                      const float* __restrict__ w_out,
                      const float* __restrict__ b_out,
                      float* __restrict__ out) {
    int m = threadIdx.x;
    if (m < MM) {
        float acc = 0.f;
        for (int h = 0; h < HH; ++h) {
            float sm = g_stats[4*2*HH + h];
            float sq = g_stats[4*2*HH + HH + h];
            float mean = sm * NMINV;
            float var  = sq * NMINV - mean*mean;
            float r  = rsqrtf(var + BN_EPS);
            float sc = gamma4[h] * r;
            float shv = beta4[h] - mean*sc;
            float ph = fmaf(sc, g_pool[m*HH + h] / (float)NN, shv);
            acc += w_out[h] * ph;
        }
        float v = acc + b_out[0];
        out[m] = 1.f / (1.f + expf(-v));
    }
}

// ---------------- launch ----------------
extern "C" void kernel_launch(void* const* d_in, const int* in_sizes, int n_in,
                              void* d_out, int out_size) {
    const float* x     = (const float*)d_in[0];
    const int*   ei    = (const int*)d_in[1];
    const float* w1_0  = (const float*)d_in[3];
    const float* w1    = (const float*)d_in[4];
    const float* b1    = (const float*)d_in[5];
    const float* w2    = (const float*)d_in[6];
    const float* b2    = (const float*)d_in[7];
    const float* gamma = (const float*)d_in[8];
    const float* beta  = (const float*)d_in[9];
    const float* w_out = (const float*)d_in[10];
    const float* b_out = (const float*)d_in[11];
    float*       out   = (float*)d_out;

    cudaFuncSetAttribute(k_mlp_mma<1>,  cudaFuncAttributeMaxDynamicSharedMemorySize, DSMEM);
    cudaFuncSetAttribute(k_mlp_mma<HH>, cudaFuncAttributeMaxDynamicSharedMemorySize, DSMEM);

    // CSR build
    k_zero_init<<<(NN + 255)/256, 256>>>();
    k_hist<<<(EE + 255)/256, 256>>>(ei);
    k_scan<<<1, 1024>>>();
    k_fill<<<(EE + 255)/256, 256>>>(ei);

    // layer 0 (aggregation + GEMM1 fused into staging)
    k_mlp_mma<1><<<NTILES, 128, DSMEM>>>(x, w1_0, b1, w2, b2, 0);

    // layers 1..4
    for (int i = 1; i < 5; ++i) {
        k_aggbn<<<NN, 128>>>(i-1, gamma + (i-1)*HH, beta + (i-1)*HH);
        k_mlp_mma<HH><<<NTILES, 128, DSMEM>>>(nullptr, w1 + (i-1)*HH*HH, b1 + i*HH,
                                              w2 + i*HH*HH, b2 + i*HH, i);
    }

    k_pool<<<(NN + 127)/128, 512>>>();
    k_out<<<1, 32>>>(gamma + 4*HH, beta + 4*HH, w_out, b_out, out);
}